// round 16
// baseline (speedup 1.0000x reference)
#include <cuda_runtime.h>
#include <stdint.h>

// Problem shape (fixed by the dataset)
#define B_DIM 8
#define K_DIM 4
#define N_DIM 131072
#define BKN   (B_DIM * K_DIM * N_DIM)   // 4,194,304

#define NEG_PAD  (-1000.0f)
#define NEG_IDLE (-100000000.0f)

// Tiling: 1024 blocks x 256 threads x 16 elements/thread
#define TPB   256
#define EPT   16
#define NPB   (TPB * EPT)               // 4096 elements per block
#define NBLK  (BKN / NPB)               // 1024
#define BLKS_PER_BK (N_DIM / NPB)       // 32 blocks per (b,k) row

// Device scratch (allocation-free rule: __device__ globals)
__device__ unsigned int d_cntS[NBLK];
__device__ unsigned int d_cntA[NBLK];
__device__ unsigned int d_offS[NBLK];
__device__ unsigned int d_offA[NBLK];
__device__ unsigned long long d_probe;
__device__ int d_mode;   // 0 = 1-byte mask elements, 1 = 4-byte mask elements

// ---------------------------------------------------------------------------
// Mask dtype probe: count nonzero bytes in the first BKN bytes of the surface
// mask (always a safe read regardless of element width). If masks are 1-byte
// 0/1 this equals ts exactly; if 4-byte it cannot equal ts.
// ---------------------------------------------------------------------------
__global__ void k_init() { d_probe = 0ULL; }

__global__ __launch_bounds__(256) void k_probe(const uint4* __restrict__ p) {
    unsigned int local = 0;
    const int nvec = BKN / 16;
    for (int i = blockIdx.x * blockDim.x + threadIdx.x; i < nvec;
         i += gridDim.x * blockDim.x) {
        uint4 v = __ldg(p + i);
        unsigned int s = __vminu4(v.x, 0x01010101u) + __vminu4(v.y, 0x01010101u) +
                         __vminu4(v.z, 0x01010101u) + __vminu4(v.w, 0x01010101u);
        local += __dp4a(s, 0x01010101u, 0u);
    }
    #pragma unroll
    for (int o = 16; o > 0; o >>= 1)
        local += __shfl_down_sync(0xFFFFFFFFu, local, o);
    if ((threadIdx.x & 31) == 0)
        atomicAdd(&d_probe, (unsigned long long)local);
}

__global__ void k_mode(unsigned long long ts) {
    d_mode = (d_probe == ts) ? 0 : 1;
}

// ---------------------------------------------------------------------------
// Mode-switched loader: 16 consecutive mask elements -> bool[16].
// base is an element index, multiple of 16 (alignment holds in both modes).
// In 4-byte mode "true" <=> word != 0 (covers int32 1 and float32 1.0f).
// ---------------------------------------------------------------------------
__device__ __forceinline__ void load_mask16(const uint8_t* __restrict__ m,
                                            int base, int mode, bool* out) {
    if (mode == 0) {
        uint4 v = __ldg(reinterpret_cast<const uint4*>(m + base));
        const unsigned int* w = reinterpret_cast<const unsigned int*>(&v);
        #pragma unroll
        for (int g = 0; g < 4; g++)
            #pragma unroll
            for (int j = 0; j < 4; j++)
                out[g * 4 + j] = ((w[g] >> (8 * j)) & 0xFFu) != 0u;
    } else {
        #pragma unroll
        for (int g = 0; g < 4; g++) {
            uint4 v = __ldg(reinterpret_cast<const uint4*>(
                m + (size_t)(base + g * 4) * 4u));
            out[g * 4 + 0] = (v.x != 0u);
            out[g * 4 + 1] = (v.y != 0u);
            out[g * 4 + 2] = (v.z != 0u);
            out[g * 4 + 3] = (v.w != 0u);
        }
    }
}

// Warp inclusive scan
__device__ __forceinline__ unsigned int warp_inscan(unsigned int v, int lane) {
    #pragma unroll
    for (int o = 1; o < 32; o <<= 1) {
        unsigned int y = __shfl_up_sync(0xFFFFFFFFu, v, o);
        if (lane >= o) v += y;
    }
    return v;
}

// ---------------------------------------------------------------------------
// Phase 1: per-block mask popcounts
// ---------------------------------------------------------------------------
__global__ __launch_bounds__(TPB) void k_count(const uint8_t* __restrict__ mS,
                                               const uint8_t* __restrict__ mA) {
    const int blk = blockIdx.x;
    const int t   = threadIdx.x;
    const int base = blk * NPB + t * EPT;
    const int mode = d_mode;

    bool bs[EPT], ba[EPT];
    load_mask16(mS, base, mode, bs);
    load_mask16(mA, base, mode, ba);

    unsigned int cS = 0, cA = 0;
    #pragma unroll
    for (int i = 0; i < EPT; i++) { cS += bs[i]; cA += ba[i]; }

    #pragma unroll
    for (int o = 16; o > 0; o >>= 1) {
        cS += __shfl_down_sync(0xFFFFFFFFu, cS, o);
        cA += __shfl_down_sync(0xFFFFFFFFu, cA, o);
    }

    __shared__ unsigned int sS[TPB / 32], sA[TPB / 32];
    if ((t & 31) == 0) { sS[t >> 5] = cS; sA[t >> 5] = cA; }
    __syncthreads();
    if (t == 0) {
        unsigned int xs = 0, xa = 0;
        #pragma unroll
        for (int i = 0; i < TPB / 32; i++) { xs += sS[i]; xa += sA[i]; }
        d_cntS[blk] = xs;
        d_cntA[blk] = xa;
    }
}

// ---------------------------------------------------------------------------
// Phase 2: exclusive scan of the 1024 block counts (single block)
// ---------------------------------------------------------------------------
__global__ __launch_bounds__(1024) void k_scan() {
    const int t = threadIdx.x;          // 0..1023
    const int lane = t & 31;
    const int warp = t >> 5;

    unsigned int vS = d_cntS[t];
    unsigned int vA = d_cntA[t];
    unsigned int sS = warp_inscan(vS, lane);
    unsigned int sA = warp_inscan(vA, lane);

    __shared__ unsigned int wS[32], wA[32];
    if (lane == 31) { wS[warp] = sS; wA[warp] = sA; }
    __syncthreads();
    if (warp == 0) {
        unsigned int x = wS[lane];
        unsigned int y = wA[lane];
        x = warp_inscan(x, lane);
        y = warp_inscan(y, lane);
        wS[lane] = x; wA[lane] = y;
    }
    __syncthreads();
    unsigned int addS = (warp > 0) ? wS[warp - 1] : 0u;
    unsigned int addA = (warp > 0) ? wA[warp - 1] : 0u;

    d_offS[t] = addS + sS - vS;   // exclusive prefix
    d_offA[t] = addA + sA - vA;
}

// ---------------------------------------------------------------------------
// Phase 3: gather + scale + emit
// ---------------------------------------------------------------------------
__global__ __launch_bounds__(TPB) void k_emit(const float* __restrict__ rgb,
                                              const float* __restrict__ lsrf,
                                              const float* __restrict__ lair,
                                              const float* __restrict__ idle,
                                              const uint8_t* __restrict__ mS,
                                              const uint8_t* __restrict__ mA,
                                              float* __restrict__ out) {
    const int blk = blockIdx.x;
    const int t   = threadIdx.x;
    const int lane = t & 31;
    const int warp = t >> 5;
    const int base = blk * NPB + t * EPT;
    const int mode = d_mode;

    bool bs[EPT], ba[EPT];
    load_mask16(mS, base, mode, bs);
    load_mask16(mA, base, mode, ba);

    unsigned int cS = 0, cA = 0;
    #pragma unroll
    for (int i = 0; i < EPT; i++) { cS += bs[i]; cA += ba[i]; }

    // Warp exclusive scan of per-thread counts
    unsigned int iS = warp_inscan(cS, lane);
    unsigned int iA = warp_inscan(cA, lane);
    unsigned int exS = iS - cS;
    unsigned int exA = iA - cA;

    __shared__ unsigned int wS[TPB / 32], wA[TPB / 32];
    if (lane == 31) { wS[warp] = iS; wA[warp] = iA; }
    __syncthreads();
    unsigned int woS = 0, woA = 0;
    #pragma unroll
    for (int i = 0; i < TPB / 32; i++) {
        if (i < warp) { woS += wS[i]; woA += wA[i]; }
    }

    unsigned int pS = d_offS[blk] + woS + exS;   // global compacted index (surface)
    unsigned int pA = d_offA[blk] + woA + exA;   // global compacted index (air)

    const int bk = blk / BLKS_PER_BK;            // (b,k) row, constant per block
    const float id    = __ldg(idle + bk);
    const float alive = 1.0f - id;
    const float idleAdd = id * NEG_IDLE;

    float* __restrict__ rgb_out = out;                       // [BKN][3]
    float* __restrict__ ls_out  = out + (size_t)3 * BKN;     // [BKN]
    float* __restrict__ la_out  = out + (size_t)4 * BKN;     // [BKN]

    #pragma unroll
    for (int g = 0; g < 4; g++) {
        const int e0 = base + g * 4;             // first element of this group of 4

        float rgbv[12];
        float4 lsv, lav;
        float* lsp = reinterpret_cast<float*>(&lsv);
        float* lap = reinterpret_cast<float*>(&lav);

        #pragma unroll
        for (int j = 0; j < 4; j++) {
            const int e = g * 4 + j;
            if (bs[e]) {
                const float* rp = rgb + (size_t)pS * 3;
                rgbv[j * 3 + 0] = __ldg(rp + 0) * alive;
                rgbv[j * 3 + 1] = __ldg(rp + 1) * alive;
                rgbv[j * 3 + 2] = __ldg(rp + 2) * alive;
                lsp[j] = __ldg(lsrf + pS) * alive + idleAdd;
                pS++;
            } else {
                rgbv[j * 3 + 0] = 0.0f;
                rgbv[j * 3 + 1] = 0.0f;
                rgbv[j * 3 + 2] = 0.0f;
                lsp[j] = NEG_PAD;
            }
            if (ba[e]) {
                lap[j] = __ldg(lair + pA) * alive + idleAdd;
                pA++;
            } else {
                lap[j] = NEG_PAD;
            }
        }

        float4* rdst = reinterpret_cast<float4*>(rgb_out + (size_t)e0 * 3);
        rdst[0] = *reinterpret_cast<float4*>(&rgbv[0]);
        rdst[1] = *reinterpret_cast<float4*>(&rgbv[4]);
        rdst[2] = *reinterpret_cast<float4*>(&rgbv[8]);
        *reinterpret_cast<float4*>(ls_out + e0) = lsv;
        *reinterpret_cast<float4*>(la_out + e0) = lav;
    }
}

// ---------------------------------------------------------------------------
// Launch
// ---------------------------------------------------------------------------
extern "C" void kernel_launch(void* const* d_in, const int* in_sizes, int n_in,
                              void* d_out, int out_size) {
    const float*   rgb  = (const float*)d_in[0];   // (ts, 3)
    const float*   lsrf = (const float*)d_in[1];   // (ts, 1)
    const float*   lair = (const float*)d_in[2];   // (ta, 1)
    const float*   idle = (const float*)d_in[3];   // (B, K) float32
    const uint8_t* mS   = (const uint8_t*)d_in[4]; // (B,K,N) bool (width TBD)
    const uint8_t* mA   = (const uint8_t*)d_in[5]; // (B,K,N) bool (width TBD)
    float* out = (float*)d_out;                    // 5*BKN floats: rgb | ls | la

    (void)n_in; (void)out_size;
    const unsigned long long ts = (unsigned long long)in_sizes[1]; // (ts,1)

    k_init<<<1, 1>>>();
    k_probe<<<256, 256>>>((const uint4*)mS);
    k_mode<<<1, 1>>>(ts);
    k_count<<<NBLK, TPB>>>(mS, mA);
    k_scan<<<1, 1024>>>();
    k_emit<<<NBLK, TPB>>>(rgb, lsrf, lair, idle, mS, mA, out);
}

// round 17
// speedup vs baseline: 1.5450x; 1.5450x over previous
#include <cuda_runtime.h>
#include <stdint.h>

// Problem shape (fixed by the dataset)
#define B_DIM 8
#define K_DIM 4
#define N_DIM 131072
#define BKN   (B_DIM * K_DIM * N_DIM)   // 4,194,304

#define NEG_PAD  (-1000.0f)
#define NEG_IDLE (-100000000.0f)

// Masks confirmed 4-byte elements (R15: mode=1 selected, rel_err == 0.0).
// "true" <=> 32-bit word != 0 (covers int32 1 and float32 1.0f).

// Tiling: 4096 blocks x 256 threads x 4 elements/thread = 4,194,304
#define TPB   256
#define EPT   4
#define NPB   (TPB * EPT)               // 1024 elements per block
#define NBLK  (BKN / NPB)               // 4096
#define BLKS_PER_BK (N_DIM / NPB)       // 128 blocks per (b,k) row

// Device scratch (allocation-free rule: __device__ globals)
__device__ unsigned int d_cntS[NBLK];
__device__ unsigned int d_cntA[NBLK];
__device__ unsigned int d_offS[NBLK];
__device__ unsigned int d_offA[NBLK];

// Warp inclusive scan
__device__ __forceinline__ unsigned int warp_inscan(unsigned int v, int lane) {
    #pragma unroll
    for (int o = 1; o < 32; o <<= 1) {
        unsigned int y = __shfl_up_sync(0xFFFFFFFFu, v, o);
        if (lane >= o) v += y;
    }
    return v;
}

__device__ __forceinline__ unsigned int count4(uint4 v) {
    return (v.x != 0u) + (v.y != 0u) + (v.z != 0u) + (v.w != 0u);
}

// ---------------------------------------------------------------------------
// Phase 1: per-block mask popcounts. One uint4 (4 elements) per thread per
// mask, lane-consecutive -> 512 B contiguous per warp per load.
// ---------------------------------------------------------------------------
__global__ __launch_bounds__(TPB) void k_count(const uint4* __restrict__ mS4,
                                               const uint4* __restrict__ mA4) {
    const int blk = blockIdx.x;
    const int t   = threadIdx.x;
    const int vi  = blk * TPB + t;      // uint4 index == element/4

    unsigned int cS = count4(__ldg(mS4 + vi));
    unsigned int cA = count4(__ldg(mA4 + vi));

    #pragma unroll
    for (int o = 16; o > 0; o >>= 1) {
        cS += __shfl_down_sync(0xFFFFFFFFu, cS, o);
        cA += __shfl_down_sync(0xFFFFFFFFu, cA, o);
    }

    __shared__ unsigned int sS[TPB / 32], sA[TPB / 32];
    if ((t & 31) == 0) { sS[t >> 5] = cS; sA[t >> 5] = cA; }
    __syncthreads();
    if (t == 0) {
        unsigned int xs = 0, xa = 0;
        #pragma unroll
        for (int i = 0; i < TPB / 32; i++) { xs += sS[i]; xa += sA[i]; }
        d_cntS[blk] = xs;
        d_cntA[blk] = xa;
    }
}

// ---------------------------------------------------------------------------
// Phase 2: exclusive scan of 4096 block counts. 1024 threads x 4 sequential.
// ---------------------------------------------------------------------------
__global__ __launch_bounds__(1024) void k_scan() {
    const int t = threadIdx.x;          // 0..1023
    const int lane = t & 31;
    const int warp = t >> 5;

    unsigned int vS[4], vA[4];
    unsigned int sumS = 0, sumA = 0;
    #pragma unroll
    for (int i = 0; i < 4; i++) {
        vS[i] = d_cntS[t * 4 + i];
        vA[i] = d_cntA[t * 4 + i];
        sumS += vS[i];
        sumA += vA[i];
    }

    unsigned int iS = warp_inscan(sumS, lane);
    unsigned int iA = warp_inscan(sumA, lane);

    __shared__ unsigned int wS[32], wA[32];
    if (lane == 31) { wS[warp] = iS; wA[warp] = iA; }
    __syncthreads();
    if (warp == 0) {
        unsigned int x = wS[lane];
        unsigned int y = wA[lane];
        x = warp_inscan(x, lane);
        y = warp_inscan(y, lane);
        wS[lane] = x; wA[lane] = y;
    }
    __syncthreads();
    unsigned int baseS = ((warp > 0) ? wS[warp - 1] : 0u) + iS - sumS;
    unsigned int baseA = ((warp > 0) ? wA[warp - 1] : 0u) + iA - sumA;

    #pragma unroll
    for (int i = 0; i < 4; i++) {
        d_offS[t * 4 + i] = baseS;
        d_offA[t * 4 + i] = baseA;
        baseS += vS[i];
        baseA += vA[i];
    }
}

// ---------------------------------------------------------------------------
// Phase 3: gather + scale + emit. 4 consecutive elements per thread:
//   masks : 1 uint4 / lane, coalesced
//   ls/la : 1 float4 / lane, perfectly coalesced
//   rgb   : 3 float4 / lane at 48 B lane stride (contiguous 1536 B per warp)
// ---------------------------------------------------------------------------
__global__ __launch_bounds__(TPB) void k_emit(const float* __restrict__ rgb,
                                              const float* __restrict__ lsrf,
                                              const float* __restrict__ lair,
                                              const float* __restrict__ idle,
                                              const uint4* __restrict__ mS4,
                                              const uint4* __restrict__ mA4,
                                              float* __restrict__ out) {
    const int blk = blockIdx.x;
    const int t   = threadIdx.x;
    const int lane = t & 31;
    const int warp = t >> 5;
    const int vi   = blk * TPB + t;     // uint4 index
    const int base = vi * EPT;          // first element owned by this thread

    const uint4 msv = __ldg(mS4 + vi);
    const uint4 mav = __ldg(mA4 + vi);

    bool bs[4] = { msv.x != 0u, msv.y != 0u, msv.z != 0u, msv.w != 0u };
    bool ba[4] = { mav.x != 0u, mav.y != 0u, mav.z != 0u, mav.w != 0u };

    unsigned int cS = bs[0] + bs[1] + bs[2] + bs[3];
    unsigned int cA = ba[0] + ba[1] + ba[2] + ba[3];

    // Warp exclusive scan of per-thread counts
    unsigned int iS = warp_inscan(cS, lane);
    unsigned int iA = warp_inscan(cA, lane);
    unsigned int exS = iS - cS;
    unsigned int exA = iA - cA;

    __shared__ unsigned int wS[TPB / 32], wA[TPB / 32];
    if (lane == 31) { wS[warp] = iS; wA[warp] = iA; }
    __syncthreads();
    unsigned int woS = 0, woA = 0;
    #pragma unroll
    for (int i = 0; i < TPB / 32; i++) {
        if (i < warp) { woS += wS[i]; woA += wA[i]; }
    }

    unsigned int pS = d_offS[blk] + woS + exS;   // global compacted index (surface)
    unsigned int pA = d_offA[blk] + woA + exA;   // global compacted index (air)

    const int bk = blk / BLKS_PER_BK;            // (b,k) row, constant per block
    const float id    = __ldg(idle + bk);
    const float alive = 1.0f - id;
    const float idleAdd = id * NEG_IDLE;

    float* __restrict__ rgb_out = out;                       // [BKN][3]
    float* __restrict__ ls_out  = out + (size_t)3 * BKN;     // [BKN]
    float* __restrict__ la_out  = out + (size_t)4 * BKN;     // [BKN]

    float rgbv[12];
    float4 lsv, lav;
    float* lsp = reinterpret_cast<float*>(&lsv);
    float* lap = reinterpret_cast<float*>(&lav);

    #pragma unroll
    for (int j = 0; j < 4; j++) {
        if (bs[j]) {
            const float* rp = rgb + (size_t)pS * 3;
            rgbv[j * 3 + 0] = __ldg(rp + 0) * alive;
            rgbv[j * 3 + 1] = __ldg(rp + 1) * alive;
            rgbv[j * 3 + 2] = __ldg(rp + 2) * alive;
            lsp[j] = __ldg(lsrf + pS) * alive + idleAdd;
            pS++;
        } else {
            rgbv[j * 3 + 0] = 0.0f;
            rgbv[j * 3 + 1] = 0.0f;
            rgbv[j * 3 + 2] = 0.0f;
            lsp[j] = NEG_PAD;
        }
        if (ba[j]) {
            lap[j] = __ldg(lair + pA) * alive + idleAdd;
            pA++;
        } else {
            lap[j] = NEG_PAD;
        }
    }

    float4* rdst = reinterpret_cast<float4*>(rgb_out + (size_t)base * 3);
    rdst[0] = *reinterpret_cast<float4*>(&rgbv[0]);
    rdst[1] = *reinterpret_cast<float4*>(&rgbv[4]);
    rdst[2] = *reinterpret_cast<float4*>(&rgbv[8]);
    *reinterpret_cast<float4*>(ls_out + base) = lsv;
    *reinterpret_cast<float4*>(la_out + base) = lav;
}

// ---------------------------------------------------------------------------
// Launch
// ---------------------------------------------------------------------------
extern "C" void kernel_launch(void* const* d_in, const int* in_sizes, int n_in,
                              void* d_out, int out_size) {
    const float* rgb  = (const float*)d_in[0];   // (ts, 3)
    const float* lsrf = (const float*)d_in[1];   // (ts, 1)
    const float* lair = (const float*)d_in[2];   // (ta, 1)
    const float* idle = (const float*)d_in[3];   // (B, K) float32
    const uint4* mS4  = (const uint4*)d_in[4];   // (B,K,N) mask, 4-byte elems
    const uint4* mA4  = (const uint4*)d_in[5];   // (B,K,N) mask, 4-byte elems
    float* out = (float*)d_out;                  // 5*BKN floats: rgb | ls | la

    (void)in_sizes; (void)n_in; (void)out_size;

    k_count<<<NBLK, TPB>>>(mS4, mA4);
    k_scan<<<1, 1024>>>();
    k_emit<<<NBLK, TPB>>>(rgb, lsrf, lair, idle, mS4, mA4, out);
}